// round 16
// baseline (speedup 1.0000x reference)
#include <cuda_runtime.h>
#include <cuda_fp16.h>
#include <cstdint>
#include <math.h>

#define B_  8
#define C_  512
#define T_  4096
#define G_  32
#define CPG 16

typedef __half half_t;

// ---------------- scratch (device globals; allocation-free rule) ------------
__device__ half_t g_hT [(size_t)B_ * T_ * C_];        // groupnorm out  [b][t][c]
__device__ half_t g_qkT[(size_t)B_ * T_ * 2 * C_];    // q,k            [b][t][0:1024)
__device__ half_t g_v  [(size_t)B_ * C_ * T_];        // v              [b][c][t]
__device__ half_t g_s  [(size_t)B_ * T_ * T_];        // exp-scores     [b][t][s] 268 MB
__device__ half_t g_aoT[(size_t)B_ * T_ * C_];        // attn@V         [b][t][c]
__device__ half_t g_wq [3 * C_ * C_];
__device__ half_t g_wp [C_ * C_];
__device__ float  g_sc [B_ * C_];
__device__ float  g_sh [B_ * C_];
__device__ float  g_rowsum[B_ * T_];                  // per-row sum of exp
__device__ int    g_tick[8];                          // per-GEMM ticket counters

#define SOFTMAX_M 8.0f

// ---------------- helpers ----------------------------------------------------
__device__ __forceinline__ uint32_t smem_u32(const void* p) {
    uint32_t a;
    asm("{ .reg .u64 t; cvta.to.shared.u64 t, %1; cvt.u32.u64 %0, t; }" : "=r"(a) : "l"(p));
    return a;
}
__device__ __forceinline__ void mma16(float* d, const uint32_t* a, const uint32_t* b) {
    asm volatile(
        "mma.sync.aligned.m16n8k16.row.col.f32.f16.f16.f32 "
        "{%0,%1,%2,%3}, {%4,%5,%6,%7}, {%8,%9}, {%0,%1,%2,%3};"
        : "+f"(d[0]), "+f"(d[1]), "+f"(d[2]), "+f"(d[3])
        : "r"(a[0]), "r"(a[1]), "r"(a[2]), "r"(a[3]), "r"(b[0]), "r"(b[1]));
}
__device__ __forceinline__ void ldsm4(uint32_t* r, uint32_t addr) {
    asm volatile("ldmatrix.sync.aligned.m8n8.x4.shared.b16 {%0,%1,%2,%3}, [%4];"
        : "=r"(r[0]), "=r"(r[1]), "=r"(r[2]), "=r"(r[3]) : "r"(addr));
}
__device__ __forceinline__ void cpa16(uint32_t dst, const void* src) {
    asm volatile("cp.async.cg.shared.global [%0], [%1], 16;" :: "r"(dst), "l"(src));
}
#define CPA_COMMIT() asm volatile("cp.async.commit_group;" ::: "memory")
__device__ __forceinline__ int slot4(int r, int c4) { return r * 32 + (c4 ^ ((r >> 2) & 7)); }

// ---------------- persistent fp16 mma GEMM ----------------------------------
// D[m,n] = alpha*sum_k A[m,k]*B[n,k]; tiles (z, m-tile, n-tile), n fastest.
// Grid = 296 persistent CTAs; tiles claimed via atomic ticket. 3-stage cp.async
// ring runs CONTINUOUSLY across tile boundaries (no fill bubble per tile).
// BM=BN=128, BK=64, 256 thr (8 warps, 64x32 warp tile), 2 CTAs/SM.
// OUTF32: f32 store (+res). BIASCOL: bias by col, else by row.
// EXPSUM: store exp(v-M) fp16 + atomic per-row exp-sums. SCALEROW: scale by 1/rowsum.
template<bool OUTF32, bool BIASCOL, bool EXPSUM, bool SCALEROW>
__global__ __launch_bounds__(256, 2) void gemm_f16(
    const half_t* __restrict__ A, const half_t* __restrict__ Bm,
    void* __restrict__ D, const float* __restrict__ bias, const float* __restrict__ res,
    float* __restrict__ rowsum, int* __restrict__ ticket,
    int K, int lda, int ldb, int ldd,
    size_t sA, size_t sB, size_t sD, size_t sR, float alpha,
    int MT, int NT, int ZT)
{
    constexpr int ROWB   = 144;                 // bytes per 64-half row
    constexpr int ABYTES = 128 * ROWB;
    constexpr int STAGEB = 2 * ABYTES;          // 36864
    extern __shared__ __align__(16) uint32_t smw[];
    __shared__ int s_nxt;
    const uint32_t sb = smem_u32(smw);
    const int tid = threadIdx.x, lane = tid & 31, wid = tid >> 5;
    const int m_off = (wid & 1) * 64, n_off = (wid >> 1) * 32;
    const int g = lane >> 2, tig = lane & 3;
    const int row16 = lane & 15, half_ = lane >> 4;
    const int total = ZT * MT * NT;
    const int nkt = K / 64;
    const int r_ = tid >> 3, c_ = tid & 7;

    auto issue_tile = [&](int tile, int kt, int stg) {
        if (tile < total) {
            int z = tile / (MT * NT);
            int r = tile - z * MT * NT;
            int mt = r / NT, nt = r - mt * NT;
            const half_t* as = A  + sA * (size_t)z + (size_t)(mt * 128) * lda + kt * 64;
            const half_t* bs = Bm + sB * (size_t)z + (size_t)(nt * 128) * ldb + kt * 64;
            const uint32_t stb = sb + stg * STAGEB;
            #pragma unroll
            for (int i = 0; i < 4; ++i) {
                const int row = r_ + 32 * i;
                cpa16(stb + row * ROWB + c_ * 16,          as + (size_t)row * lda + c_ * 8);
                cpa16(stb + ABYTES + row * ROWB + c_ * 16, bs + (size_t)row * ldb + c_ * 8);
            }
        }
        CPA_COMMIT();
    };

    float acc[4][4][4];
    int cur = blockIdx.x;
    int seq = 0;
    issue_tile(cur, 0, 0);
    issue_tile(cur, 1, 1);

    while (cur < total) {
        #pragma unroll
        for (int i = 0; i < 4; ++i)
            #pragma unroll
            for (int j = 0; j < 4; ++j)
                #pragma unroll
                for (int e = 0; e < 4; ++e) acc[i][j][e] = 0.f;

        for (int kt = 0; kt < nkt; ++kt, ++seq) {
            asm volatile("cp.async.wait_group 1;" ::: "memory");
            __syncthreads();
            if (kt == 0 && tid == 0)
                s_nxt = (int)gridDim.x + atomicAdd(ticket, 1);
            // issue k-tile kt+2 (spills into the next tile's first k-tiles)
            int t2 = cur, k2 = kt + 2;
            if (k2 >= nkt) { k2 -= nkt; t2 = s_nxt; }   // s_nxt stable: written kt==0, read kt>=nkt-2>=1
            issue_tile(t2, k2, (seq + 2) % 3);
            // compute stage seq%3
            {
                const uint32_t base  = sb + (seq % 3) * STAGEB;
                const uint32_t aBase = base + (m_off + row16) * ROWB + half_ * 16;
                const uint32_t bBase = base + ABYTES + (n_off + row16) * ROWB + half_ * 16;
                #pragma unroll
                for (int ks = 0; ks < 4; ++ks) {
                    uint32_t af[4][4], bq[2][4];
                    #pragma unroll
                    for (int mt = 0; mt < 4; ++mt) ldsm4(af[mt], aBase + mt * (16 * ROWB) + ks * 32);
                    #pragma unroll
                    for (int p = 0; p < 2; ++p)    ldsm4(bq[p], bBase + p * (16 * ROWB) + ks * 32);
                    #pragma unroll
                    for (int mt = 0; mt < 4; ++mt)
                        #pragma unroll
                        for (int nt = 0; nt < 4; ++nt) {
                            uint32_t bfr[2] = { bq[nt >> 1][nt & 1], bq[nt >> 1][(nt & 1) + 2] };
                            mma16(acc[mt][nt], af[mt], bfr);
                        }
                }
            }
        }

        // ---------------- epilogue for tile 'cur' ----------------
        {
            int z = cur / (MT * NT);
            int r = cur - z * MT * NT;
            int m0 = (r / NT) * 128, n0 = (r - (r / NT) * NT) * 128;
            #pragma unroll
            for (int mt = 0; mt < 4; ++mt) {
                const int rml = m_off + mt * 16 + g;
                float rb0 = 0.f, rb1 = 0.f;
                if (!BIASCOL && bias) { rb0 = bias[m0 + rml]; rb1 = bias[m0 + rml + 8]; }
                float inv0 = 1.f, inv1 = 1.f;
                if (SCALEROW) {
                    inv0 = 1.0f / rowsum[z * T_ + m0 + rml];
                    inv1 = 1.0f / rowsum[z * T_ + m0 + rml + 8];
                }
                float s0 = 0.f, s1 = 0.f;
                #pragma unroll
                for (int nt = 0; nt < 4; ++nt) {
                    const int col = n0 + n_off + nt * 8 + 2 * tig;
                    float2 cb = make_float2(0.f, 0.f);
                    if (BIASCOL && bias) cb = *reinterpret_cast<const float2*>(bias + col);
                    float v0x = alpha * acc[mt][nt][0], v0y = alpha * acc[mt][nt][1];
                    float v1x = alpha * acc[mt][nt][2], v1y = alpha * acc[mt][nt][3];
                    if (BIASCOL) { v0x += cb.x; v0y += cb.y; v1x += cb.x; v1y += cb.y; }
                    else         { v0x += rb0;  v0y += rb0;  v1x += rb1;  v1y += rb1;  }
                    if (EXPSUM) {
                        v0x = __expf(v0x - SOFTMAX_M); v0y = __expf(v0y - SOFTMAX_M);
                        v1x = __expf(v1x - SOFTMAX_M); v1y = __expf(v1y - SOFTMAX_M);
                        s0 += v0x + v0y; s1 += v1x + v1y;
                    }
                    if (SCALEROW) { v0x *= inv0; v0y *= inv0; v1x *= inv1; v1y *= inv1; }
                    size_t i0 = (size_t)(m0 + rml)     * ldd + col;
                    size_t i1 = (size_t)(m0 + rml + 8) * ldd + col;
                    if (OUTF32) {
                        float* dst = (float*)D + sD * (size_t)z;
                        if (res) {
                            const float* rp = res + sR * (size_t)z;
                            float2 r0 = *reinterpret_cast<const float2*>(rp + i0);
                            float2 r1 = *reinterpret_cast<const float2*>(rp + i1);
                            v0x += r0.x; v0y += r0.y; v1x += r1.x; v1y += r1.y;
                        }
                        *reinterpret_cast<float2*>(dst + i0) = make_float2(v0x, v0y);
                        *reinterpret_cast<float2*>(dst + i1) = make_float2(v1x, v1y);
                    } else {
                        half_t* dst = (half_t*)D + sD * (size_t)z;
                        *reinterpret_cast<__half2*>(dst + i0) = __float22half2_rn(make_float2(v0x, v0y));
                        *reinterpret_cast<__half2*>(dst + i1) = __float22half2_rn(make_float2(v1x, v1y));
                    }
                }
                if (EXPSUM) {
                    s0 += __shfl_xor_sync(0xFFFFFFFF, s0, 1);
                    s0 += __shfl_xor_sync(0xFFFFFFFF, s0, 2);
                    s1 += __shfl_xor_sync(0xFFFFFFFF, s1, 1);
                    s1 += __shfl_xor_sync(0xFFFFFFFF, s1, 2);
                    if (tig == 0) {
                        atomicAdd(&rowsum[z * T_ + m0 + rml],     s0);
                        atomicAdd(&rowsum[z * T_ + m0 + rml + 8], s1);
                    }
                }
            }
        }
        cur = s_nxt;   // stable: next write only after next kt==0 barrier
    }
    asm volatile("cp.async.wait_group 0;" ::: "memory");
}

// ---------------- fp32 -> fp16 weight convert -------------------------------
__global__ void cvt_kernel(const float* __restrict__ src, half_t* __restrict__ dst, int n4) {
    int i = blockIdx.x * 256 + threadIdx.x;
    if (i < n4) {
        float4 v = reinterpret_cast<const float4*>(src)[i];
        __half2 a = __float22half2_rn(make_float2(v.x, v.y));
        __half2 b = __float22half2_rn(make_float2(v.z, v.w));
        reinterpret_cast<uint2*>(dst)[i] = make_uint2(
            *reinterpret_cast<uint32_t*>(&a), *reinterpret_cast<uint32_t*>(&b));
    }
}

// ---------------- GroupNorm pass 1 ------------------------------------------
__global__ __launch_bounds__(256) void gn_stats(const float* __restrict__ x,
                                                const float* __restrict__ w,
                                                const float* __restrict__ bb,
                                                float* __restrict__ sc,
                                                float* __restrict__ sh) {
    const int bg = blockIdx.x;
    const int bi = bg >> 5;
    const int g  = bg & 31;
    const size_t base = ((size_t)bi * C_ + (size_t)g * CPG) * T_;
    const float4* xp4 = reinterpret_cast<const float4*>(x + base);
    const int n4 = CPG * T_ / 4;
    float s = 0.f, s2 = 0.f;
    for (int i = threadIdx.x; i < n4; i += 256) {
        float4 v = xp4[i];
        s  += v.x + v.y + v.z + v.w;
        s2 += v.x * v.x + v.y * v.y + v.z * v.z + v.w * v.w;
    }
    __shared__ float rs[256], rq[256];
    rs[threadIdx.x] = s; rq[threadIdx.x] = s2;
    __syncthreads();
    for (int off = 128; off > 0; off >>= 1) {
        if (threadIdx.x < off) {
            rs[threadIdx.x] += rs[threadIdx.x + off];
            rq[threadIdx.x] += rq[threadIdx.x + off];
        }
        __syncthreads();
    }
    const float inv_n = 1.0f / (float)(CPG * T_);
    const float mean  = rs[0] * inv_n;
    const float var   = rq[0] * inv_n - mean * mean;
    const float rstd  = rsqrtf(var + 1e-5f);
    if (threadIdx.x < CPG) {
        int c = g * CPG + threadIdx.x;
        float scv = w[c] * rstd;
        sc[bi * C_ + c] = scv;
        sh[bi * C_ + c] = bb[c] - mean * scv;
    }
}

// ---------------- GroupNorm pass 2: normalize + transpose -> fp16 hT --------
__global__ __launch_bounds__(256) void gn_tr(const float* __restrict__ x,
                                             const float* __restrict__ sc,
                                             const float* __restrict__ sh,
                                             half_t* __restrict__ hT) {
    __shared__ float smf[64 * 128];
    const int t0 = blockIdx.x * 128, c0 = blockIdx.y * 64, z = blockIdx.z;
    const int tid = threadIdx.x;
    #pragma unroll 2
    for (int i = 0; i < 8; ++i) {
        int q = tid + 256 * i;
        int row = q >> 5, t4 = q & 31;           // row = local c (0..63)
        int c = c0 + row;
        float scv = sc[z * C_ + c], shv = sh[z * C_ + c];
        float4 v = *reinterpret_cast<const float4*>(
            x + ((size_t)z * C_ + c) * T_ + t0 + 4 * t4);
        v.x = v.x * scv + shv; v.y = v.y * scv + shv;
        v.z = v.z * scv + shv; v.w = v.w * scv + shv;
        *reinterpret_cast<float4*>(smf + 4 * slot4(row, t4)) = v;
    }
    __syncthreads();
    #pragma unroll 2
    for (int i = 0; i < 8; ++i) {
        int oq = tid + 256 * i;
        int t = oq >> 4, c4 = oq & 15;           // 4 channels per item
        float4 v;
        v.x = smf[4 * slot4(4 * c4 + 0, t >> 2) + (t & 3)];
        v.y = smf[4 * slot4(4 * c4 + 1, t >> 2) + (t & 3)];
        v.z = smf[4 * slot4(4 * c4 + 2, t >> 2) + (t & 3)];
        v.w = smf[4 * slot4(4 * c4 + 3, t >> 2) + (t & 3)];
        __half2 a = __float22half2_rn(make_float2(v.x, v.y));
        __half2 b = __float22half2_rn(make_float2(v.z, v.w));
        *reinterpret_cast<uint2*>(hT + ((size_t)z * T_ + t0 + t) * C_ + c0 + 4 * c4) =
            make_uint2(*reinterpret_cast<uint32_t*>(&a), *reinterpret_cast<uint32_t*>(&b));
    }
}

// ---------------------------------------------------------------------------
extern "C" void kernel_launch(void* const* d_in, const int* in_sizes, int n_in,
                              void* d_out, int out_size) {
    const float* x      = (const float*)d_in[0];
    const float* gn_w   = (const float*)d_in[1];
    const float* gn_b   = (const float*)d_in[2];
    const float* qkv_w  = (const float*)d_in[3];
    const float* qkv_b  = (const float*)d_in[4];
    const float* proj_w = (const float*)d_in[5];
    const float* proj_b = (const float*)d_in[6];
    float* out = (float*)d_out;

    half_t *hT, *qkT, *v, *s, *aoT, *wq, *wp;
    float *sc, *sh, *rowsum;
    int *tick;
    cudaGetSymbolAddress((void**)&hT,  g_hT);
    cudaGetSymbolAddress((void**)&qkT, g_qkT);
    cudaGetSymbolAddress((void**)&v,   g_v);
    cudaGetSymbolAddress((void**)&s,   g_s);
    cudaGetSymbolAddress((void**)&aoT, g_aoT);
    cudaGetSymbolAddress((void**)&wq,  g_wq);
    cudaGetSymbolAddress((void**)&wp,  g_wp);
    cudaGetSymbolAddress((void**)&sc,  g_sc);
    cudaGetSymbolAddress((void**)&sh,  g_sh);
    cudaGetSymbolAddress((void**)&rowsum, g_rowsum);
    cudaGetSymbolAddress((void**)&tick, g_tick);

    const int GSM = 3 * 36864;   // 108 KB
    cudaFuncSetAttribute(gemm_f16<false, true,  false, false>, cudaFuncAttributeMaxDynamicSharedMemorySize, GSM);
    cudaFuncSetAttribute(gemm_f16<false, false, false, false>, cudaFuncAttributeMaxDynamicSharedMemorySize, GSM);
    cudaFuncSetAttribute(gemm_f16<false, false, true,  false>, cudaFuncAttributeMaxDynamicSharedMemorySize, GSM);
    cudaFuncSetAttribute(gemm_f16<false, false, false, true >, cudaFuncAttributeMaxDynamicSharedMemorySize, GSM);
    cudaFuncSetAttribute(gemm_f16<true,  false, false, false>, cudaFuncAttributeMaxDynamicSharedMemorySize, GSM);

    const size_t CT  = (size_t)C_ * T_;
    const size_t TT  = (size_t)T_ * T_;
    const size_t TC  = (size_t)T_ * C_;
    const size_t T2C = (size_t)T_ * 2 * C_;
    const int NCTA = 296;   // 2 CTAs/SM x 148 SMs

    // 0) weight conversion; zero rowsum + tickets
    cvt_kernel<<<(3 * C_ * C_ / 4 + 255) / 256, 256>>>(qkv_w, wq, 3 * C_ * C_ / 4);
    cvt_kernel<<<(C_ * C_ / 4 + 255) / 256, 256>>>(proj_w, wp, C_ * C_ / 4);
    cudaMemsetAsync(rowsum, 0, B_ * T_ * sizeof(float));
    cudaMemsetAsync(tick, 0, 8 * sizeof(int));

    // 1) GroupNorm
    gn_stats<<<B_ * G_, 256>>>(x, gn_w, gn_b, sc, sh);
    gn_tr<<<dim3(T_ / 128, C_ / 64, B_), 256>>>(x, sc, sh, hT);

    // 2a) QK: D[t,o] = hT[t,:].W[o,:] + b[o] -> qkT[t][o]  (MT=32 t, NT=8 o)
    gemm_f16<false, true, false, false><<<NCTA, 256, GSM>>>(
        hT, wq, qkT, qkv_b, nullptr, nullptr, tick + 0,
        C_, C_, C_, 2 * C_,
        TC, 0, T2C, 0, 1.0f, 32, 8, B_);

    // 2b) V: D[c,t] = Wv[c,:].hT[t,:] + b -> v[c][t]  (MT=4 c, NT=32 t)
    gemm_f16<false, false, false, false><<<NCTA, 256, GSM>>>(
        wq + 2 * C_ * C_, hT, v, qkv_b + 2 * C_, nullptr, nullptr, tick + 1,
        C_, C_, C_, T_,
        0, TC, CT, 0, 1.0f, 4, 32, B_);

    // 3) Exp-scores: P[t,n] = exp(alpha*q.k - M) + atomic rowsum  (MT=32, NT=32)
    gemm_f16<false, false, true, false><<<NCTA, 256, GSM>>>(
        qkT, qkT + C_, s, nullptr, nullptr, rowsum, tick + 2,
        C_, 2 * C_, 2 * C_, T_,
        T2C, T2C, TT, 0, 0.04419417382415922f, 32, 32, B_);

    // 4) AV: D[t,c] = (attn[t,:]/rowsum[t]).v[c,:] -> aoT[t][c]  (MT=32 t, NT=4 c)
    gemm_f16<false, false, false, true><<<NCTA, 256, GSM>>>(
        s, v, aoT, nullptr, nullptr, rowsum, tick + 3,
        T_, T_, T_, C_,
        TT, CT, TC, 0, 1.0f, 32, 4, B_);

    // 5) Proj: out[c,t] = Wp[c,:].aoT[t,:] + pb[c] + x  (MT=4 c, NT=32 t)
    gemm_f16<true, false, false, false><<<NCTA, 256, GSM>>>(
        wp, aoT, out, proj_b, x, nullptr, tick + 4,
        C_, C_, C_, T_,
        0, TC, CT, CT, 1.0f, 4, 32, B_);
}

// round 17
// speedup vs baseline: 1.1250x; 1.1250x over previous
#include <cuda_runtime.h>
#include <cuda_fp16.h>
#include <cstdint>
#include <math.h>

#define B_  8
#define C_  512
#define T_  4096
#define G_  32
#define CPG 16

typedef __half half_t;

// ---------------- scratch (device globals; allocation-free rule) ------------
__device__ half_t g_hT [(size_t)B_ * T_ * C_];        // groupnorm out  [b][t][c]
__device__ half_t g_qkT[(size_t)B_ * T_ * 2 * C_];    // sqrt(a)*q,k    [b][t][0:1024)
__device__ half_t g_v  [(size_t)B_ * C_ * T_];        // v              [b][c][t]
__device__ half_t g_s  [(size_t)B_ * T_ * T_];        // exp-scores     [b][t][s] 268 MB
__device__ half_t g_aoT[(size_t)B_ * T_ * C_];        // attn@V unnorm  [b][t][c]
__device__ half_t g_wq [3 * C_ * C_];
__device__ half_t g_wp [C_ * C_];
__device__ float  g_sc [B_ * C_];
__device__ float  g_sh [B_ * C_];
__device__ float  g_rowsum[B_ * T_];                  // per-row sum of exp

#define SOFTMAX_M 8.0f

// ---------------- helpers ----------------------------------------------------
__device__ __forceinline__ uint32_t smem_u32(const void* p) {
    uint32_t a;
    asm("{ .reg .u64 t; cvta.to.shared.u64 t, %1; cvt.u32.u64 %0, t; }" : "=r"(a) : "l"(p));
    return a;
}
__device__ __forceinline__ void mma16(float* d, const uint32_t* a, const uint32_t* b) {
    asm volatile(
        "mma.sync.aligned.m16n8k16.row.col.f32.f16.f16.f32 "
        "{%0,%1,%2,%3}, {%4,%5,%6,%7}, {%8,%9}, {%0,%1,%2,%3};"
        : "+f"(d[0]), "+f"(d[1]), "+f"(d[2]), "+f"(d[3])
        : "r"(a[0]), "r"(a[1]), "r"(a[2]), "r"(a[3]), "r"(b[0]), "r"(b[1]));
}
__device__ __forceinline__ void ldsm4(uint32_t* r, uint32_t addr) {
    asm volatile("ldmatrix.sync.aligned.m8n8.x4.shared.b16 {%0,%1,%2,%3}, [%4];"
        : "=r"(r[0]), "=r"(r[1]), "=r"(r[2]), "=r"(r[3]) : "r"(addr));
}
__device__ __forceinline__ void cpa16(uint32_t dst, const void* src) {
    asm volatile("cp.async.cg.shared.global [%0], [%1], 16;" :: "r"(dst), "l"(src));
}
#define CPA_COMMIT() asm volatile("cp.async.commit_group;" ::: "memory")
__device__ __forceinline__ int slot4(int r, int c4) { return r * 32 + (c4 ^ ((r >> 2) & 7)); }

// ---------------- fp16 mma GEMM: D[m,n] = alpha*sum_k A[m,k]*B[n,k] ----------
// BM=BN=128, BK=64, 256 threads (8 warps, warp tile 64x32), cp.async 3-stage,
// 2 CTAs/SM, 1 sync per 64-k tile.  (R14 champion shell.)
// smem/stage: (128+128) rows x 144B (64 halfs padded to 36 words) = 36864B.
// OUTF32: f32 store (+res). BIASCOL: bias by col (bias scaled by alpha too).
// EXPSUM: store exp(v - M) fp16 and atomicAdd per-row exp-sums into rowsum.
// SCALECOL: multiply output by 1/rowsum[col] (per-column, used by proj).
template<bool OUTF32, bool BIASCOL, bool EXPSUM, bool SCALECOL>
__global__ __launch_bounds__(256, 2) void gemm_f16(
    const half_t* __restrict__ A, const half_t* __restrict__ Bm,
    void* __restrict__ D, const float* __restrict__ bias, const float* __restrict__ res,
    float* __restrict__ rowsum,
    int K, int lda, int ldb, int ldd,
    size_t sA, size_t sB, size_t sD, size_t sR, float alpha)
{
    constexpr int ROWB   = 144;                 // bytes per 64-half row (36 words)
    constexpr int ABYTES = 128 * ROWB;          // 18432
    constexpr int STAGEB = 2 * ABYTES;          // 36864
    extern __shared__ __align__(16) uint32_t smw[];
    const uint32_t sb = smem_u32(smw);
    const int tid = threadIdx.x, lane = tid & 31, wid = tid >> 5;
    const int m_off = (wid & 1) * 64, n_off = (wid >> 1) * 32;
    const int g = lane >> 2, tig = lane & 3;
    const int row16 = lane & 15, half_ = lane >> 4;
    const int m0 = blockIdx.y * 128, n0 = blockIdx.x * 128, z = blockIdx.z;

    const half_t* Ag = A  + sA * (size_t)z + (size_t)m0 * lda;
    const half_t* Bg = Bm + sB * (size_t)z + (size_t)n0 * ldb;

    float acc[4][4][4];
    #pragma unroll
    for (int i = 0; i < 4; ++i)
        #pragma unroll
        for (int j = 0; j < 4; ++j)
            #pragma unroll
            for (int e = 0; e < 4; ++e) acc[i][j][e] = 0.f;

    const int r_ = tid >> 3, c_ = tid & 7;      // 32 rows/pass, 8 16B-chunks/row
    auto issue = [&](int t, int s) {
        const uint32_t stb = sb + s * STAGEB;
        const half_t* as = Ag + t * 64;
        const half_t* bs = Bg + t * 64;
        #pragma unroll
        for (int i = 0; i < 4; ++i) {
            const int row = r_ + 32 * i;
            cpa16(stb + row * ROWB + c_ * 16,          as + (size_t)row * lda + c_ * 8);
            cpa16(stb + ABYTES + row * ROWB + c_ * 16, bs + (size_t)row * ldb + c_ * 8);
        }
        CPA_COMMIT();
    };
    auto compute = [&](int s) {
        const uint32_t base  = sb + s * STAGEB;
        const uint32_t aBase = base + (m_off + row16) * ROWB + half_ * 16;
        const uint32_t bBase = base + ABYTES + (n_off + row16) * ROWB + half_ * 16;
        #pragma unroll
        for (int ks = 0; ks < 4; ++ks) {
            uint32_t af[4][4], bq[2][4];
            #pragma unroll
            for (int mt = 0; mt < 4; ++mt) ldsm4(af[mt], aBase + mt * (16 * ROWB) + ks * 32);
            #pragma unroll
            for (int p = 0; p < 2; ++p)    ldsm4(bq[p], bBase + p * (16 * ROWB) + ks * 32);
            #pragma unroll
            for (int mt = 0; mt < 4; ++mt)
                #pragma unroll
                for (int nt = 0; nt < 4; ++nt) {
                    uint32_t bfr[2] = { bq[nt >> 1][nt & 1], bq[nt >> 1][(nt & 1) + 2] };
                    mma16(acc[mt][nt], af[mt], bfr);
                }
        }
    };

    const int ntl = K / 64;
    issue(0, 0);
    if (ntl > 1) issue(1, 1);
    for (int t = 0; t < ntl; ++t) {
        if (t + 1 < ntl) asm volatile("cp.async.wait_group 1;" ::: "memory");
        else             asm volatile("cp.async.wait_group 0;" ::: "memory");
        __syncthreads();
        if (t + 2 < ntl) issue(t + 2, (t + 2) % 3);
        compute(t % 3);
    }

    // ---------------- epilogue ----------------
    #pragma unroll
    for (int mt = 0; mt < 4; ++mt) {
        const int rml = m_off + mt * 16 + g;
        float rb0 = 0.f, rb1 = 0.f;
        if (!BIASCOL && bias) { rb0 = bias[m0 + rml]; rb1 = bias[m0 + rml + 8]; }
        float s0 = 0.f, s1 = 0.f;
        #pragma unroll
        for (int nt = 0; nt < 4; ++nt) {
            const int col = n0 + n_off + nt * 8 + 2 * tig;
            float2 cb = make_float2(0.f, 0.f);
            if (BIASCOL && bias) cb = *reinterpret_cast<const float2*>(bias + col);
            float v0x = alpha * acc[mt][nt][0], v0y = alpha * acc[mt][nt][1];
            float v1x = alpha * acc[mt][nt][2], v1y = alpha * acc[mt][nt][3];
            if (BIASCOL) {   // bias scaled by alpha too (used for sqrt(a)-folded QK)
                v0x += alpha * cb.x; v0y += alpha * cb.y;
                v1x += alpha * cb.x; v1y += alpha * cb.y;
            } else {
                v0x += rb0;  v0y += rb0;  v1x += rb1;  v1y += rb1;
            }
            if (EXPSUM) {
                v0x = __expf(v0x - SOFTMAX_M); v0y = __expf(v0y - SOFTMAX_M);
                v1x = __expf(v1x - SOFTMAX_M); v1y = __expf(v1y - SOFTMAX_M);
                s0 += v0x + v0y; s1 += v1x + v1y;
            }
            if (SCALECOL) {  // per-column 1/rowsum (softmax denom commuted through proj)
                float2 rsv = *reinterpret_cast<const float2*>(rowsum + z * T_ + col);
                float ix = 1.0f / rsv.x, iy = 1.0f / rsv.y;
                v0x *= ix; v0y *= iy; v1x *= ix; v1y *= iy;
            }
            size_t i0 = (size_t)(m0 + rml)     * ldd + col;
            size_t i1 = (size_t)(m0 + rml + 8) * ldd + col;
            if (OUTF32) {
                float* dst = (float*)D + sD * (size_t)z;
                if (res) {
                    const float* rp = res + sR * (size_t)z;
                    float2 r0 = *reinterpret_cast<const float2*>(rp + i0);
                    float2 r1 = *reinterpret_cast<const float2*>(rp + i1);
                    v0x += r0.x; v0y += r0.y; v1x += r1.x; v1y += r1.y;
                }
                *reinterpret_cast<float2*>(dst + i0) = make_float2(v0x, v0y);
                *reinterpret_cast<float2*>(dst + i1) = make_float2(v1x, v1y);
            } else {
                half_t* dst = (half_t*)D + sD * (size_t)z;
                *reinterpret_cast<__half2*>(dst + i0) = __float22half2_rn(make_float2(v0x, v0y));
                *reinterpret_cast<__half2*>(dst + i1) = __float22half2_rn(make_float2(v1x, v1y));
            }
        }
        if (EXPSUM) {
            s0 += __shfl_xor_sync(0xFFFFFFFF, s0, 1);
            s0 += __shfl_xor_sync(0xFFFFFFFF, s0, 2);
            s1 += __shfl_xor_sync(0xFFFFFFFF, s1, 1);
            s1 += __shfl_xor_sync(0xFFFFFFFF, s1, 2);
            if (tig == 0) {
                atomicAdd(&rowsum[z * T_ + m0 + rml],     s0);
                atomicAdd(&rowsum[z * T_ + m0 + rml + 8], s1);
            }
        }
    }
}

// ---------------- fp32 -> fp16 weight convert -------------------------------
__global__ void cvt_kernel(const float* __restrict__ src, half_t* __restrict__ dst, int n4) {
    int i = blockIdx.x * 256 + threadIdx.x;
    if (i < n4) {
        float4 v = reinterpret_cast<const float4*>(src)[i];
        __half2 a = __float22half2_rn(make_float2(v.x, v.y));
        __half2 b = __float22half2_rn(make_float2(v.z, v.w));
        reinterpret_cast<uint2*>(dst)[i] = make_uint2(
            *reinterpret_cast<uint32_t*>(&a), *reinterpret_cast<uint32_t*>(&b));
    }
}

// ---------------- GroupNorm pass 1 ------------------------------------------
__global__ __launch_bounds__(256) void gn_stats(const float* __restrict__ x,
                                                const float* __restrict__ w,
                                                const float* __restrict__ bb,
                                                float* __restrict__ sc,
                                                float* __restrict__ sh) {
    const int bg = blockIdx.x;
    const int bi = bg >> 5;
    const int g  = bg & 31;
    const size_t base = ((size_t)bi * C_ + (size_t)g * CPG) * T_;
    const float4* xp4 = reinterpret_cast<const float4*>(x + base);
    const int n4 = CPG * T_ / 4;
    float s = 0.f, s2 = 0.f;
    for (int i = threadIdx.x; i < n4; i += 256) {
        float4 v = xp4[i];
        s  += v.x + v.y + v.z + v.w;
        s2 += v.x * v.x + v.y * v.y + v.z * v.z + v.w * v.w;
    }
    __shared__ float rs[256], rq[256];
    rs[threadIdx.x] = s; rq[threadIdx.x] = s2;
    __syncthreads();
    for (int off = 128; off > 0; off >>= 1) {
        if (threadIdx.x < off) {
            rs[threadIdx.x] += rs[threadIdx.x + off];
            rq[threadIdx.x] += rq[threadIdx.x + off];
        }
        __syncthreads();
    }
    const float inv_n = 1.0f / (float)(CPG * T_);
    const float mean  = rs[0] * inv_n;
    const float var   = rq[0] * inv_n - mean * mean;
    const float rstd  = rsqrtf(var + 1e-5f);
    if (threadIdx.x < CPG) {
        int c = g * CPG + threadIdx.x;
        float scv = w[c] * rstd;
        sc[bi * C_ + c] = scv;
        sh[bi * C_ + c] = bb[c] - mean * scv;
    }
}

// ---------------- GroupNorm pass 2: normalize + transpose -> fp16 hT --------
__global__ __launch_bounds__(256) void gn_tr(const float* __restrict__ x,
                                             const float* __restrict__ sc,
                                             const float* __restrict__ sh,
                                             half_t* __restrict__ hT) {
    __shared__ float smf[64 * 128];
    const int t0 = blockIdx.x * 128, c0 = blockIdx.y * 64, z = blockIdx.z;
    const int tid = threadIdx.x;
    #pragma unroll 2
    for (int i = 0; i < 8; ++i) {
        int q = tid + 256 * i;
        int row = q >> 5, t4 = q & 31;           // row = local c (0..63)
        int c = c0 + row;
        float scv = sc[z * C_ + c], shv = sh[z * C_ + c];
        float4 v = *reinterpret_cast<const float4*>(
            x + ((size_t)z * C_ + c) * T_ + t0 + 4 * t4);
        v.x = v.x * scv + shv; v.y = v.y * scv + shv;
        v.z = v.z * scv + shv; v.w = v.w * scv + shv;
        *reinterpret_cast<float4*>(smf + 4 * slot4(row, t4)) = v;
    }
    __syncthreads();
    #pragma unroll 2
    for (int i = 0; i < 8; ++i) {
        int oq = tid + 256 * i;
        int t = oq >> 4, c4 = oq & 15;           // 4 channels per item
        float4 v;
        v.x = smf[4 * slot4(4 * c4 + 0, t >> 2) + (t & 3)];
        v.y = smf[4 * slot4(4 * c4 + 1, t >> 2) + (t & 3)];
        v.z = smf[4 * slot4(4 * c4 + 2, t >> 2) + (t & 3)];
        v.w = smf[4 * slot4(4 * c4 + 3, t >> 2) + (t & 3)];
        __half2 a = __float22half2_rn(make_float2(v.x, v.y));
        __half2 b = __float22half2_rn(make_float2(v.z, v.w));
        *reinterpret_cast<uint2*>(hT + ((size_t)z * T_ + t0 + t) * C_ + c0 + 4 * c4) =
            make_uint2(*reinterpret_cast<uint32_t*>(&a), *reinterpret_cast<uint32_t*>(&b));
    }
}

// ---------------------------------------------------------------------------
extern "C" void kernel_launch(void* const* d_in, const int* in_sizes, int n_in,
                              void* d_out, int out_size) {
    const float* x      = (const float*)d_in[0];
    const float* gn_w   = (const float*)d_in[1];
    const float* gn_b   = (const float*)d_in[2];
    const float* qkv_w  = (const float*)d_in[3];
    const float* qkv_b  = (const float*)d_in[4];
    const float* proj_w = (const float*)d_in[5];
    const float* proj_b = (const float*)d_in[6];
    float* out = (float*)d_out;

    half_t *hT, *qkT, *v, *s, *aoT, *wq, *wp;
    float *sc, *sh, *rowsum;
    cudaGetSymbolAddress((void**)&hT,  g_hT);
    cudaGetSymbolAddress((void**)&qkT, g_qkT);
    cudaGetSymbolAddress((void**)&v,   g_v);
    cudaGetSymbolAddress((void**)&s,   g_s);
    cudaGetSymbolAddress((void**)&aoT, g_aoT);
    cudaGetSymbolAddress((void**)&wq,  g_wq);
    cudaGetSymbolAddress((void**)&wp,  g_wp);
    cudaGetSymbolAddress((void**)&sc,  g_sc);
    cudaGetSymbolAddress((void**)&sh,  g_sh);
    cudaGetSymbolAddress((void**)&rowsum, g_rowsum);

    const int GSM = 3 * 36864;   // 108 KB
    cudaFuncSetAttribute(gemm_f16<false, true,  false, false>, cudaFuncAttributeMaxDynamicSharedMemorySize, GSM);
    cudaFuncSetAttribute(gemm_f16<false, false, false, false>, cudaFuncAttributeMaxDynamicSharedMemorySize, GSM);
    cudaFuncSetAttribute(gemm_f16<false, false, true,  false>, cudaFuncAttributeMaxDynamicSharedMemorySize, GSM);
    cudaFuncSetAttribute(gemm_f16<true,  false, false, true >, cudaFuncAttributeMaxDynamicSharedMemorySize, GSM);

    const size_t CT  = (size_t)C_ * T_;
    const size_t TT  = (size_t)T_ * T_;
    const size_t TC  = (size_t)T_ * C_;
    const size_t T2C = (size_t)T_ * 2 * C_;
    const float SQRT_ALPHA = 0.21022410381342864f;   // (1/sqrt(512))^(1/2)

    // 0) weight conversion fp32 -> fp16; zero rowsum accumulators
    cvt_kernel<<<(3 * C_ * C_ / 4 + 255) / 256, 256>>>(qkv_w, wq, 3 * C_ * C_ / 4);
    cvt_kernel<<<(C_ * C_ / 4 + 255) / 256, 256>>>(proj_w, wp, C_ * C_ / 4);
    cudaMemsetAsync(rowsum, 0, B_ * T_ * sizeof(float));

    // 1) GroupNorm
    gn_stats<<<B_ * G_, 256>>>(x, gn_w, gn_b, sc, sh);
    gn_tr<<<dim3(T_ / 128, C_ / 64, B_), 256>>>(x, sc, sh, hT);

    // 2a) QK (alpha folded): qkT[t][o] = sqrt(a)*(hT[t,:].W[o,:] + b[o]), o<1024
    gemm_f16<false, true, false, false><<<dim3(1024 / 128, T_ / 128, B_), 256, GSM>>>(
        hT, wq, qkT, qkv_b, nullptr, nullptr,
        C_, C_, C_, 2 * C_,
        TC, 0, T2C, 0, SQRT_ALPHA);

    // 2b) V: D[c,t] = Wv[c,:].hT[t,:] + b (row bias) -> v[c][t]
    gemm_f16<false, false, false, false><<<dim3(T_ / 128, C_ / 128, B_), 256, GSM>>>(
        wq + 2 * C_ * C_, hT, v, qkv_b + 2 * C_, nullptr, nullptr,
        C_, C_, C_, T_,
        0, TC, CT, 0, 1.0f);

    // 3) Exp-scores: P[t,n] = exp(q'.k' - M), rowsum accumulated atomically
    gemm_f16<false, false, true, false><<<dim3(T_ / 128, T_ / 128, B_), 256, GSM>>>(
        qkT, qkT + C_, s, nullptr, nullptr, rowsum,
        C_, 2 * C_, 2 * C_, T_,
        T2C, T2C, TT, 0, 1.0f);

    // 4) AV (unnormalized): aoT[t][c] = P[t,:].v[c,:]
    gemm_f16<false, false, false, false><<<dim3(C_ / 128, T_ / 128, B_), 256, GSM>>>(
        s, v, aoT, nullptr, nullptr, nullptr,
        T_, T_, T_, C_,
        TT, CT, TC, 0, 1.0f);

    // 5) Proj + deferred softmax denom: out[c,t] = (Wp.aoT)[c,t]/rowsum[t] + pb[c] + x
    gemm_f16<true, false, false, true><<<dim3(T_ / 128, C_ / 128, B_), 256, GSM>>>(
        wp, aoT, out, proj_b, x, rowsum,
        C_, C_, C_, T_,
        0, TC, CT, CT, 1.0f);
}